// round 15
// baseline (speedup 1.0000x reference)
#include <cuda_runtime.h>
#include <cuda_bf16.h>
#include <cstdint>

#define HW    16384
#define BATCH 8
#define CDIM  192
#define HEADS 6
#define CH    32
#define NROWS (BATCH*CDIM)      /* 1536 */
#define NBH   (BATCH*HEADS)     /* 48   */
#define ATT_CHUNKS 8
#define ATT_CHUNK  (HW/ATT_CHUNKS)
#define WSZ   (CDIM*CDIM)       /* 36864 */
#define SZB   (CDIM*HW)         /* per-batch elements 3145728 */
#define SZ    (BATCH*SZB)       /* 25165824 */

/* ------------------------------------------------------------------ */
/* Scratch (device globals: no allocations allowed)                    */
/* ------------------------------------------------------------------ */
__device__ float g_qp[SZ];
__device__ float g_kp[SZ];
__device__ float g_attn[NBH*CH*CH];
__device__ float g_ss[2*NROWS];
__device__ __nv_bfloat16 g_wh[3*WSZ];
__device__ __nv_bfloat16 g_wl[3*WSZ];
__device__ __nv_bfloat16 g_weffh[BATCH*WSZ];
__device__ __nv_bfloat16 g_weffl[BATCH*WSZ];
__device__ __nv_bfloat16 g_xh[3*SZ];       /* pre-split q,k,v hi */
__device__ __nv_bfloat16 g_xl[3*SZ];       /* pre-split q,k,v lo */
__device__ __nv_bfloat16 g_vph[SZ];        /* vp hi (GEMM3 output) */
__device__ __nv_bfloat16 g_vpl[SZ];        /* vp lo */

/* ------------------------------------------------------------------ */
__global__ void zero_kernel() {
    int i = blockIdx.x * 256 + threadIdx.x;
    if (i < NBH*CH*CH) g_attn[i] = 0.f;
    if (i < 2*NROWS)   g_ss[i]   = 0.f;
}

__global__ void prep_w(const float* __restrict__ wq,
                       const float* __restrict__ wk,
                       const float* __restrict__ wv)
{
    int i = blockIdx.x * 256 + threadIdx.x;
    if (i >= 3*WSZ) return;
    const float* src = (i < WSZ) ? wq : (i < 2*WSZ ? wk : wv);
    float x = src[i % WSZ];
    __nv_bfloat16 h = __float2bfloat16(x);
    g_wh[i] = h;
    g_wl[i] = __float2bfloat16(x - __bfloat162float(h));
}

/* Split q,k,v into bf16 hi/lo (streaming, float4 in / uint2 out). */
__global__ void prep_x(const float* __restrict__ q,
                       const float* __restrict__ k,
                       const float* __restrict__ v)
{
    const int slot = blockIdx.y;
    const float* src = (slot == 0) ? q : (slot == 1 ? k : v);
    size_t idx = (size_t)blockIdx.x * 256 + threadIdx.x;   /* float4 idx */
    float4 xv = ((const float4*)src)[idx];
    float xs[4] = {xv.x, xv.y, xv.z, xv.w};
    uint16_t h[4], l[4];
    #pragma unroll
    for (int j = 0; j < 4; j++) {
        __nv_bfloat16 hb = __float2bfloat16(xs[j]);
        h[j] = __bfloat16_as_ushort(hb);
        l[j] = __bfloat16_as_ushort(__float2bfloat16(xs[j] - __bfloat162float(hb)));
    }
    uint2 hv = make_uint2((uint32_t)h[0] | ((uint32_t)h[1] << 16),
                          (uint32_t)h[2] | ((uint32_t)h[3] << 16));
    uint2 lv = make_uint2((uint32_t)l[0] | ((uint32_t)l[1] << 16),
                          (uint32_t)l[2] | ((uint32_t)l[3] << 16));
    ((uint2*)(g_xh + (size_t)slot * SZ))[idx] = hv;
    ((uint2*)(g_xl + (size_t)slot * SZ))[idx] = lv;
}

/* ------------------------------------------------------------------ */
/* Fully cp.async-staged bf16-split tensor-core conv1x1.
 * CTA: 192(M) x 128(N), 512 threads, 16 warps = 4(M) x 4(N),
 * warp tile 48x32. K=192 in 3 chunks of 64, double-buffered.
 * A [m][kpair] (non-trans ldm), B native [k][n] + ldmatrix.x4.trans
 * (272B row pitch -> conflict-free). Zero convert work in-kernel.    */
/* ------------------------------------------------------------------ */
#define ASTR   36                      /* A row stride, words */
#define A_HALF (192*ASTR)              /* 6912 words (hi or lo) */
#define A_BUFW (2*A_HALF)              /* 13824 */
#define B_ROWB 272                     /* B row pitch, bytes */
#define B_HALF (64*68)                 /* 4352 words */
#define B_BUFW (2*B_HALF)              /* 8704 */
#define SA_W(buf) ((buf)*A_BUFW)
#define SB_W(buf) (2*A_BUFW + (buf)*B_BUFW)
#define S_WORDS (2*A_BUFW + 2*B_BUFW)  /* 45056 words = 180224 B */

__device__ __forceinline__ uint32_t smem_u32(const void* p) {
    uint32_t a;
    asm("{ .reg .u64 t; cvta.to.shared.u64 t, %1; cvt.u32.u64 %0, t; }"
        : "=r"(a) : "l"(p));
    return a;
}
__device__ __forceinline__ void cp16(uint32_t saddr, const void* g) {
    asm volatile("cp.async.cg.shared.global [%0], [%1], 16;"
                 :: "r"(saddr), "l"(g));
}
#define CP_COMMIT() asm volatile("cp.async.commit_group;" ::: "memory")
#define CP_WAIT1()  asm volatile("cp.async.wait_group 1;" ::: "memory")
#define CP_WAIT0()  asm volatile("cp.async.wait_group 0;" ::: "memory")

__device__ __forceinline__ void ldm_x4(uint32_t* r, uint32_t addr) {
    asm volatile("ldmatrix.sync.aligned.m8n8.x4.shared.b16 {%0,%1,%2,%3}, [%4];"
        : "=r"(r[0]), "=r"(r[1]), "=r"(r[2]), "=r"(r[3]) : "r"(addr));
}
__device__ __forceinline__ void ldm_x4t(uint32_t* r, uint32_t addr) {
    asm volatile("ldmatrix.sync.aligned.m8n8.x4.trans.shared.b16 {%0,%1,%2,%3}, [%4];"
        : "=r"(r[0]), "=r"(r[1]), "=r"(r[2]), "=r"(r[3]) : "r"(addr));
}
__device__ __forceinline__ void mma_bf16(float* c, const uint32_t* a, const uint32_t* b) {
    asm volatile(
        "mma.sync.aligned.m16n8k16.row.col.f32.bf16.bf16.f32 "
        "{%0,%1,%2,%3}, {%4,%5,%6,%7}, {%8,%9}, {%0,%1,%2,%3};"
        : "+f"(c[0]), "+f"(c[1]), "+f"(c[2]), "+f"(c[3])
        : "r"(a[0]), "r"(a[1]), "r"(a[2]), "r"(a[3]), "r"(b[0]), "r"(b[1]));
}

__global__ void __launch_bounds__(512, 1)
gemm_bf16(const __nv_bfloat16* __restrict__ Xhi,
          const __nv_bfloat16* __restrict__ Xlo,
          const __nv_bfloat16* __restrict__ Whi,
          const __nv_bfloat16* __restrict__ Wlo,
          const float* __restrict__ bias,
          float* __restrict__ Yf,
          __nv_bfloat16* __restrict__ Yh,
          __nv_bfloat16* __restrict__ Yl,
          int wstride, int out_split)
{
    extern __shared__ uint32_t sm[];
    const uint32_t sbase = smem_u32(sm);

    const int tid  = threadIdx.x;
    const int wid  = tid >> 5;
    const int lane = tid & 31;
    const int grp  = lane >> 2;
    const int tig  = lane & 3;
    const int wm   = wid & 3;
    const int wn   = wid >> 2;

    const int n0 = blockIdx.x * 128;
    const int b  = blockIdx.y;

    const __nv_bfloat16* Xbh = Xhi + (size_t)b * SZB;
    const __nv_bfloat16* Xbl = Xlo + (size_t)b * SZB;
    const __nv_bfloat16* Wh  = Whi + (size_t)b * wstride;
    const __nv_bfloat16* Wl  = Wlo + (size_t)b * wstride;

    /* ldmatrix addressing */
    const int a_row  = lane & 15;
    const int a_koff = (lane >> 4) * 4;
    const int b_kr   = lane & 15;            /* k row within 16 */
    const int b_noff = (lane >> 4) * 8;      /* n +8 for matrices 2,3 */

    float acc[3][4][4];
    #pragma unroll
    for (int i = 0; i < 3; i++)
        #pragma unroll
        for (int j = 0; j < 4; j++)
            #pragma unroll
            for (int r = 0; r < 4; r++) acc[i][j][r] = 0.f;

    /* ---- pure cp.async staging of one chunk into buf ---- */
    auto stage = [&](int k0, int buf) {
        /* A: 192 m-rows x 8 chunks x {hi,lo} = 3072 cp16, 6/thread */
        #pragma unroll
        for (int r = 0; r < 3; r++) {
            int j = tid + 512*r;            /* 0..1535 */
            int m = j >> 3, kg = j & 7;
            cp16(sbase + (SA_W(buf) + m*ASTR + kg*4)*4,
                 Wh + m*CDIM + k0 + 8*kg);
            cp16(sbase + (SA_W(buf) + A_HALF + m*ASTR + kg*4)*4,
                 Wl + m*CDIM + k0 + 8*kg);
        }
        /* B: 64 k-rows x 16 chunks x {hi,lo} = 2048 cp16, 4/thread */
        #pragma unroll
        for (int r = 0; r < 2; r++) {
            int j = tid + 512*r;            /* 0..1023 */
            int k = j >> 4, jg = j & 15;
            cp16(sbase + SB_W(buf)*4 + k*B_ROWB + jg*16,
                 Xbh + (size_t)(k0 + k) * HW + n0 + 8*jg);
            cp16(sbase + (SB_W(buf) + B_HALF)*4 + k*B_ROWB + jg*16,
                 Xbl + (size_t)(k0 + k) * HW + n0 + 8*jg);
        }
    };

    stage(0, 0);
    CP_COMMIT();

    for (int c = 0; c < 3; c++) {
        const int cur = c & 1;
        if (c < 2) { stage((c + 1) * 64, cur ^ 1); CP_COMMIT(); CP_WAIT1(); }
        else       { CP_WAIT0(); }
        __syncthreads();                 /* buf[cur] visible to all */

        const uint32_t abase = sbase + SA_W(cur)*4;
        const uint32_t bbase = sbase + SB_W(cur)*4;
        #pragma unroll
        for (int s = 0; s < 4; s++) {
            uint32_t ah[3][4], al[3][4], bh[2][4], bl[2][4];
            #pragma unroll
            for (int mf = 0; mf < 3; mf++) {
                uint32_t off = ((wm*48 + mf*16 + a_row)*ASTR + s*8 + a_koff) * 4;
                ldm_x4(ah[mf], abase + off);
                ldm_x4(al[mf], abase + A_HALF*4 + off);
            }
            #pragma unroll
            for (int np = 0; np < 2; np++) {
                uint32_t off = (uint32_t)(s*16 + b_kr) * B_ROWB
                             + (uint32_t)(wn*32 + np*16 + b_noff) * 2;
                ldm_x4t(bh[np], bbase + off);
                ldm_x4t(bl[np], bbase + B_HALF*4 + off);
            }
            #pragma unroll
            for (int mf = 0; mf < 3; mf++)
                #pragma unroll
                for (int nf = 0; nf < 4; nf++) {
                    const uint32_t* pbh = &bh[nf>>1][(nf&1)*2];
                    const uint32_t* pbl = &bl[nf>>1][(nf&1)*2];
                    mma_bf16(acc[mf][nf], ah[mf], pbh);
                    mma_bf16(acc[mf][nf], ah[mf], pbl);
                    mma_bf16(acc[mf][nf], al[mf], pbh);
                }
        }
        __syncthreads();                 /* reads done before re-stage */
    }

    /* epilogue */
    #pragma unroll
    for (int mf = 0; mf < 3; mf++) {
        int mr = wm*48 + mf*16 + grp;
        float bz0 = __ldg(&bias[mr]);
        float bz1 = __ldg(&bias[mr + 8]);
        #pragma unroll
        for (int nf = 0; nf < 4; nf++) {
            int n = n0 + wn*32 + nf*8 + tig*2;
            float x0 = acc[mf][nf][0] + bz0, x1 = acc[mf][nf][1] + bz0;
            float x2 = acc[mf][nf][2] + bz1, x3 = acc[mf][nf][3] + bz1;
            if (!out_split) {
                float* Yb = Yf + (size_t)b * SZB;
                *(float2*)&Yb[(size_t)mr * HW + n]       = make_float2(x0, x1);
                *(float2*)&Yb[(size_t)(mr + 8) * HW + n] = make_float2(x2, x3);
            } else {
                __nv_bfloat16* Ybh = Yh + (size_t)b * SZB;
                __nv_bfloat16* Ybl = Yl + (size_t)b * SZB;
                __nv_bfloat16 h0 = __float2bfloat16(x0), h1 = __float2bfloat16(x1);
                __nv_bfloat16 h2 = __float2bfloat16(x2), h3 = __float2bfloat16(x3);
                uint32_t hv0 = (uint32_t)__bfloat16_as_ushort(h0)
                             | ((uint32_t)__bfloat16_as_ushort(h1) << 16);
                uint32_t hv1 = (uint32_t)__bfloat16_as_ushort(h2)
                             | ((uint32_t)__bfloat16_as_ushort(h3) << 16);
                uint32_t lv0 = (uint32_t)__bfloat16_as_ushort(
                                   __float2bfloat16(x0 - __bfloat162float(h0)))
                             | ((uint32_t)__bfloat16_as_ushort(
                                   __float2bfloat16(x1 - __bfloat162float(h1))) << 16);
                uint32_t lv1 = (uint32_t)__bfloat16_as_ushort(
                                   __float2bfloat16(x2 - __bfloat162float(h2)))
                             | ((uint32_t)__bfloat16_as_ushort(
                                   __float2bfloat16(x3 - __bfloat162float(h3))) << 16);
                *(uint32_t*)&Ybh[(size_t)mr * HW + n]       = hv0;
                *(uint32_t*)&Ybh[(size_t)(mr + 8) * HW + n] = hv1;
                *(uint32_t*)&Ybl[(size_t)mr * HW + n]       = lv0;
                *(uint32_t*)&Ybl[(size_t)(mr + 8) * HW + n] = lv1;
            }
        }
    }
}

/* ------------------------------------------------------------------ */
/* Fused raw logits + row sum-of-squares, float4-vectorized.           */
/* ------------------------------------------------------------------ */
__global__ void __launch_bounds__(256)
attn_kernel(const float* __restrict__ qp, const float* __restrict__ kp)
{
    const int bh   = blockIdx.x;
    const int ch   = blockIdx.y;
    const int warp = threadIdx.x >> 5;
    const int lane = threadIdx.x & 31;
    const int b  = bh / HEADS;
    const int hh = bh % HEADS;

    const float* Q = qp + (size_t)(b*CDIM + hh*CH) * HW;
    const float* K = kp + (size_t)(b*CDIM + hh*CH) * HW;
    const int c0 = warp * 4;

    float acc[4][32];
    #pragma unroll
    for (int i = 0; i < 4; i++)
        #pragma unroll
        for (int d = 0; d < 32; d++) acc[i][d] = 0.f;
    float qs[4] = {0.f,0.f,0.f,0.f};
    float ks[4] = {0.f,0.f,0.f,0.f};

    const int v0 = (ch * ATT_CHUNK) >> 2;
    for (int n = v0 + lane; n < v0 + (ATT_CHUNK >> 2); n += 32) {
        float4 qv[4];
        #pragma unroll
        for (int i = 0; i < 4; i++) {
            qv[i] = ((const float4*)(Q + (size_t)(c0 + i) * HW))[n];
            qs[i] += qv[i].x*qv[i].x + qv[i].y*qv[i].y
                   + qv[i].z*qv[i].z + qv[i].w*qv[i].w;
        }
        #pragma unroll
        for (int i = 0; i < 4; i++) {
            float4 kc = ((const float4*)(K + (size_t)(c0 + i) * HW))[n];
            ks[i] += kc.x*kc.x + kc.y*kc.y + kc.z*kc.z + kc.w*kc.w;
        }
        #pragma unroll
        for (int d = 0; d < 32; d++) {
            float4 kv = ((const float4*)(K + (size_t)d * HW))[n];
            #pragma unroll
            for (int i = 0; i < 4; i++)
                acc[i][d] += qv[i].x*kv.x + qv[i].y*kv.y
                           + qv[i].z*kv.z + qv[i].w*kv.w;
        }
    }

    #pragma unroll
    for (int i = 0; i < 4; i++) {
        float out = 0.f;
        #pragma unroll
        for (int d = 0; d < 32; d++) {
            float v = acc[i][d];
            v += __shfl_xor_sync(0xffffffffu, v, 16);
            v += __shfl_xor_sync(0xffffffffu, v, 8);
            v += __shfl_xor_sync(0xffffffffu, v, 4);
            v += __shfl_xor_sync(0xffffffffu, v, 2);
            v += __shfl_xor_sync(0xffffffffu, v, 1);
            if (lane == d) out = v;
        }
        atomicAdd(&g_attn[bh*CH*CH + (c0 + i)*CH + lane], out);
    }

    #pragma unroll
    for (int i = 0; i < 4; i++) {
        float vq = qs[i], vk = ks[i];
        vq += __shfl_xor_sync(0xffffffffu, vq, 16);
        vq += __shfl_xor_sync(0xffffffffu, vq, 8);
        vq += __shfl_xor_sync(0xffffffffu, vq, 4);
        vq += __shfl_xor_sync(0xffffffffu, vq, 2);
        vq += __shfl_xor_sync(0xffffffffu, vq, 1);
        vk += __shfl_xor_sync(0xffffffffu, vk, 16);
        vk += __shfl_xor_sync(0xffffffffu, vk, 8);
        vk += __shfl_xor_sync(0xffffffffu, vk, 4);
        vk += __shfl_xor_sync(0xffffffffu, vk, 2);
        vk += __shfl_xor_sync(0xffffffffu, vk, 1);
        if (lane == 0) {
            int row = b*CDIM + hh*CH + c0 + i;
            atomicAdd(&g_ss[row], vq);
            atomicAdd(&g_ss[NROWS + row], vk);
        }
    }
}

/* ------------------------------------------------------------------ */
__global__ void softmax_kernel(const float* __restrict__ temp)
{
    const int bh = blockIdx.x;
    const int b  = bh / HEADS;
    const int hh = bh % HEADS;
    const int c  = threadIdx.y;
    const int d  = threadIdx.x;

    const int rowq = b*CDIM + hh*CH + c;
    const int rowk = b*CDIM + hh*CH + d;
    float rq = 1.f / fmaxf(sqrtf(g_ss[rowq]), 1e-12f);
    float rk = 1.f / fmaxf(sqrtf(g_ss[NROWS + rowk]), 1e-12f);

    int idx = bh*CH*CH + c*CH + d;
    float v = g_attn[idx] * rq * rk * temp[hh];

    float m = v;
    m = fmaxf(m, __shfl_xor_sync(0xffffffffu, m, 16));
    m = fmaxf(m, __shfl_xor_sync(0xffffffffu, m, 8));
    m = fmaxf(m, __shfl_xor_sync(0xffffffffu, m, 4));
    m = fmaxf(m, __shfl_xor_sync(0xffffffffu, m, 2));
    m = fmaxf(m, __shfl_xor_sync(0xffffffffu, m, 1));
    float e = __expf(v - m);
    float s = e;
    s += __shfl_xor_sync(0xffffffffu, s, 16);
    s += __shfl_xor_sync(0xffffffffu, s, 8);
    s += __shfl_xor_sync(0xffffffffu, s, 4);
    s += __shfl_xor_sync(0xffffffffu, s, 2);
    s += __shfl_xor_sync(0xffffffffu, s, 1);
    g_attn[idx] = e / s;
}

/* ------------------------------------------------------------------ */
__global__ void weff_kernel(const float* __restrict__ wo)
{
    const int b   = blockIdx.y;
    const int idx = blockIdx.x * 256 + threadIdx.x;
    const int o   = idx / CDIM;
    const int dg  = idx % CDIM;
    const int h   = dg / CH;
    const int dc  = dg % CH;

    const float* P    = g_attn + ((b*HEADS + h)*CH)*CH;
    const float* wrow = wo + o*CDIM + h*CH;
    float s = 0.f;
    #pragma unroll
    for (int c = 0; c < CH; c++)
        s += wrow[c] * P[c*CH + dc];

    size_t off = (size_t)b*WSZ + o*CDIM + dg;
    __nv_bfloat16 hw = __float2bfloat16(s);
    g_weffh[off] = hw;
    g_weffl[off] = __float2bfloat16(s - __bfloat162float(hw));
}

/* ------------------------------------------------------------------ */
extern "C" void kernel_launch(void* const* d_in, const int* in_sizes, int n_in,
                              void* d_out, int out_size)
{
    const float* q    = (const float*)d_in[0];
    const float* k    = (const float*)d_in[1];
    const float* v    = (const float*)d_in[2];
    const float* wq   = (const float*)d_in[3];
    const float* bq   = (const float*)d_in[4];
    const float* wk   = (const float*)d_in[5];
    const float* bk   = (const float*)d_in[6];
    const float* wv   = (const float*)d_in[7];
    const float* bv   = (const float*)d_in[8];
    const float* wo   = (const float*)d_in[9];
    const float* bo   = (const float*)d_in[10];
    const float* temp = (const float*)d_in[11];

    float *qp, *kp;
    __nv_bfloat16 *wh, *wl, *weh, *wel, *xh, *xl, *vph, *vpl;
    cudaGetSymbolAddress((void**)&qp,  g_qp);
    cudaGetSymbolAddress((void**)&kp,  g_kp);
    cudaGetSymbolAddress((void**)&wh,  g_wh);
    cudaGetSymbolAddress((void**)&wl,  g_wl);
    cudaGetSymbolAddress((void**)&weh, g_weffh);
    cudaGetSymbolAddress((void**)&wel, g_weffl);
    cudaGetSymbolAddress((void**)&xh,  g_xh);
    cudaGetSymbolAddress((void**)&xl,  g_xl);
    cudaGetSymbolAddress((void**)&vph, g_vph);
    cudaGetSymbolAddress((void**)&vpl, g_vpl);

    const int smem_bytes = S_WORDS * 4;
    cudaFuncSetAttribute(gemm_bf16, cudaFuncAttributeMaxDynamicSharedMemorySize,
                         smem_bytes);

    zero_kernel<<<(NBH*CH*CH + 255)/256, 256>>>();
    prep_w<<<(3*WSZ + 255)/256, 256>>>(wq, wk, wv);
    prep_x<<<dim3(SZ/4/256, 3), 256>>>(q, k, v);

    dim3 gg(HW/128, BATCH);
    gemm_bf16<<<gg, 512, smem_bytes>>>(xh + 0*(size_t)SZ, xl + 0*(size_t)SZ,
                                       wh + 0*WSZ, wl + 0*WSZ, bq,
                                       qp, (__nv_bfloat16*)0, (__nv_bfloat16*)0, 0, 0);
    gemm_bf16<<<gg, 512, smem_bytes>>>(xh + 1*(size_t)SZ, xl + 1*(size_t)SZ,
                                       wh + 1*WSZ, wl + 1*WSZ, bk,
                                       kp, (__nv_bfloat16*)0, (__nv_bfloat16*)0, 0, 0);
    gemm_bf16<<<gg, 512, smem_bytes>>>(xh + 2*(size_t)SZ, xl + 2*(size_t)SZ,
                                       wh + 2*WSZ, wl + 2*WSZ, bv,
                                       (float*)0, vph, vpl, 0, 1);

    attn_kernel<<<dim3(NBH, ATT_CHUNKS), 256>>>(qp, kp);
    softmax_kernel<<<NBH, dim3(32, 32)>>>(temp);
    weff_kernel<<<dim3((CDIM*CDIM)/256, BATCH), 256>>>(wo);

    gemm_bf16<<<gg, 512, smem_bytes>>>(vph, vpl, weh, wel, bo,
                                       (float*)d_out, (__nv_bfloat16*)0,
                                       (__nv_bfloat16*)0, WSZ, 0);
}

// round 16
// speedup vs baseline: 1.1447x; 1.1447x over previous
#include <cuda_runtime.h>
#include <cuda_bf16.h>
#include <cstdint>

#define HW    16384
#define BATCH 8
#define CDIM  192
#define HEADS 6
#define CH    32
#define NROWS (BATCH*CDIM)      /* 1536 */
#define NBH   (BATCH*HEADS)     /* 48   */
#define ATT_CHUNKS 8
#define ATT_CHUNK  (HW/ATT_CHUNKS)
#define WSZ   (CDIM*CDIM)       /* 36864 */
#define SZB   (CDIM*HW)         /* 3145728 */
#define SZ    (BATCH*SZB)

/* ------------------------------------------------------------------ */
__device__ float g_qp[SZ];
__device__ float g_kp[SZ];
__device__ float g_attn[NBH*CH*CH];
__device__ float g_ss[2*NROWS];
__device__ __nv_bfloat16 g_wh[3*WSZ];
__device__ __nv_bfloat16 g_wl[3*WSZ];
__device__ __nv_bfloat16 g_weffh[BATCH*WSZ];
__device__ __nv_bfloat16 g_weffl[BATCH*WSZ];
__device__ __nv_bfloat16 g_vph[SZ];
__device__ __nv_bfloat16 g_vpl[SZ];

/* ------------------------------------------------------------------ */
__global__ void zero_kernel() {
    int i = blockIdx.x * 256 + threadIdx.x;
    if (i < NBH*CH*CH) g_attn[i] = 0.f;
    if (i < 2*NROWS)   g_ss[i]   = 0.f;
}

__global__ void prep_w(const float* __restrict__ wq,
                       const float* __restrict__ wk,
                       const float* __restrict__ wv)
{
    int i = blockIdx.x * 256 + threadIdx.x;
    if (i >= 3*WSZ) return;
    const float* src = (i < WSZ) ? wq : (i < 2*WSZ ? wk : wv);
    float x = src[i % WSZ];
    __nv_bfloat16 h = __float2bfloat16(x);
    g_wh[i] = h;
    g_wl[i] = __float2bfloat16(x - __bfloat162float(h));
}

/* ------------------------------------------------------------------ */
/* Unified bf16-split tensor-core conv1x1.
 * CTA: 192(M) x 128(N), 512 threads, 16 warps = 4(M) x 4(N).
 * K=192 in 3 chunks, double-buffered, ONE barrier per chunk.
 * A (pre-split weights): always cp.async.
 * B: IN_SPLIT ? cp.async from pre-split : LDG fp32 + truncation split
 *    (1 PRMT + 1 LOP + 1 FADD + shared CVT per elem) into the SAME
 *    [k][n] 272B-pitch layout -> ldmatrix.x4.trans either way.       */
/* ------------------------------------------------------------------ */
#define ASTR   36
#define A_HALF (192*ASTR)              /* 6912 words */
#define A_BUFW (2*A_HALF)
#define B_ROWB 272
#define B_HALF (64*68)                 /* 4352 words */
#define B_BUFW (2*B_HALF)
#define SA_W(buf) ((buf)*A_BUFW)
#define SB_W(buf) (2*A_BUFW + (buf)*B_BUFW)
#define S_WORDS (2*A_BUFW + 2*B_BUFW)  /* 45056 words = 180224 B */

__device__ __forceinline__ uint32_t smem_u32(const void* p) {
    uint32_t a;
    asm("{ .reg .u64 t; cvta.to.shared.u64 t, %1; cvt.u32.u64 %0, t; }"
        : "=r"(a) : "l"(p));
    return a;
}
__device__ __forceinline__ void cp16(uint32_t saddr, const void* g) {
    asm volatile("cp.async.cg.shared.global [%0], [%1], 16;"
                 :: "r"(saddr), "l"(g));
}
#define CP_COMMIT() asm volatile("cp.async.commit_group;" ::: "memory")
#define CP_WAIT0()  asm volatile("cp.async.wait_group 0;" ::: "memory")

__device__ __forceinline__ void ldm_x4(uint32_t* r, uint32_t addr) {
    asm volatile("ldmatrix.sync.aligned.m8n8.x4.shared.b16 {%0,%1,%2,%3}, [%4];"
        : "=r"(r[0]), "=r"(r[1]), "=r"(r[2]), "=r"(r[3]) : "r"(addr));
}
__device__ __forceinline__ void ldm_x4t(uint32_t* r, uint32_t addr) {
    asm volatile("ldmatrix.sync.aligned.m8n8.x4.trans.shared.b16 {%0,%1,%2,%3}, [%4];"
        : "=r"(r[0]), "=r"(r[1]), "=r"(r[2]), "=r"(r[3]) : "r"(addr));
}
__device__ __forceinline__ void mma_bf16(float* c, const uint32_t* a, const uint32_t* b) {
    asm volatile(
        "mma.sync.aligned.m16n8k16.row.col.f32.bf16.bf16.f32 "
        "{%0,%1,%2,%3}, {%4,%5,%6,%7}, {%8,%9}, {%0,%1,%2,%3};"
        : "+f"(c[0]), "+f"(c[1]), "+f"(c[2]), "+f"(c[3])
        : "r"(a[0]), "r"(a[1]), "r"(a[2]), "r"(a[3]), "r"(b[0]), "r"(b[1]));
}

template<int IN_SPLIT, int OUT_SPLIT>
__global__ void __launch_bounds__(512, 1)
gemm_bf16(const float* __restrict__ Xf,
          const __nv_bfloat16* __restrict__ Xhi,
          const __nv_bfloat16* __restrict__ Xlo,
          const __nv_bfloat16* __restrict__ Whi,
          const __nv_bfloat16* __restrict__ Wlo,
          const float* __restrict__ bias,
          float* __restrict__ Yf,
          __nv_bfloat16* __restrict__ Yh,
          __nv_bfloat16* __restrict__ Yl,
          int wstride)
{
    extern __shared__ uint32_t sm[];
    char* smc = (char*)sm;
    const uint32_t sbase = smem_u32(sm);

    const int tid  = threadIdx.x;
    const int wid  = tid >> 5;
    const int lane = tid & 31;
    const int grp  = lane >> 2;
    const int tig  = lane & 3;
    const int wm   = wid & 3;
    const int wn   = wid >> 2;

    const int n0 = blockIdx.x * 128;
    const int b  = blockIdx.y;

    const float* Xbf = Xf ? Xf + (size_t)b * SZB : (const float*)0;
    const __nv_bfloat16* Xbh = Xhi ? Xhi + (size_t)b * SZB : (const __nv_bfloat16*)0;
    const __nv_bfloat16* Xbl = Xlo ? Xlo + (size_t)b * SZB : (const __nv_bfloat16*)0;
    const __nv_bfloat16* Wh  = Whi + (size_t)b * wstride;
    const __nv_bfloat16* Wl  = Wlo + (size_t)b * wstride;

    const int a_row  = lane & 15;
    const int a_koff = (lane >> 4) * 4;
    const int b_kr   = lane & 15;
    const int b_noff = (lane >> 4) * 8;

    float acc[3][4][4];
    #pragma unroll
    for (int i = 0; i < 3; i++)
        #pragma unroll
        for (int j = 0; j < 4; j++)
            #pragma unroll
            for (int r = 0; r < 4; r++) acc[i][j][r] = 0.f;

    auto stage = [&](int k0, int buf) {
        /* A: 192 x 8 kgroups x {hi,lo}, cp.async */
        #pragma unroll
        for (int r = 0; r < 3; r++) {
            int j = tid + 512*r;
            int m = j >> 3, kg = j & 7;
            cp16(sbase + (SA_W(buf) + m*ASTR + kg*4)*4, Wh + m*CDIM + k0 + 8*kg);
            cp16(sbase + (SA_W(buf) + A_HALF + m*ASTR + kg*4)*4, Wl + m*CDIM + k0 + 8*kg);
        }
        if (IN_SPLIT) {
            /* B pre-split: pure cp.async into [k][n] layout */
            #pragma unroll
            for (int r = 0; r < 2; r++) {
                int j = tid + 512*r;
                int k = j >> 4, jg = j & 15;
                cp16(sbase + SB_W(buf)*4 + k*B_ROWB + jg*16,
                     Xbh + (size_t)(k0 + k) * HW + n0 + 8*jg);
                cp16(sbase + (SB_W(buf) + B_HALF)*4 + k*B_ROWB + jg*16,
                     Xbl + (size_t)(k0 + k) * HW + n0 + 8*jg);
            }
        } else {
            /* B fp32: truncation split into [k][n] layout */
            #pragma unroll
            for (int r = 0; r < 2; r++) {
                int j = tid + 512*r;
                int k = j >> 4, seg = j & 15;
                const float* xp = Xbf + (size_t)(k0 + k) * HW + n0 + 8*seg;
                float4 xa = *(const float4*)xp;
                float4 xb = *(const float4*)(xp + 4);
                float xs[8] = {xa.x,xa.y,xa.z,xa.w,xb.x,xb.y,xb.z,xb.w};
                uint32_t hw4[4], lw4[4];
                #pragma unroll
                for (int p = 0; p < 4; p++) {
                    uint32_t b0 = __float_as_uint(xs[2*p]);
                    uint32_t b1 = __float_as_uint(xs[2*p+1]);
                    hw4[p] = __byte_perm(b0, b1, 0x7632);
                    float h0 = __uint_as_float(b0 & 0xFFFF0000u);
                    float h1 = __uint_as_float(b1 & 0xFFFF0000u);
                    __nv_bfloat162 lo2 = __floats2bfloat162_rn(xs[2*p] - h0, xs[2*p+1] - h1);
                    lw4[p] = *reinterpret_cast<uint32_t*>(&lo2);
                }
                *(uint4*)(smc + SB_W(buf)*4 + k*B_ROWB + seg*16) =
                    make_uint4(hw4[0],hw4[1],hw4[2],hw4[3]);
                *(uint4*)(smc + (SB_W(buf) + B_HALF)*4 + k*B_ROWB + seg*16) =
                    make_uint4(lw4[0],lw4[1],lw4[2],lw4[3]);
            }
        }
    };

    stage(0, 0);
    CP_COMMIT();
    CP_WAIT0();
    __syncthreads();

    for (int c = 0; c < 3; c++) {
        const int cur = c & 1;
        if (c < 2) { stage((c + 1) * 64, cur ^ 1); CP_COMMIT(); }

        const uint32_t abase = sbase + SA_W(cur)*4;
        const uint32_t bbase = sbase + SB_W(cur)*4;
        #pragma unroll
        for (int s = 0; s < 4; s++) {
            uint32_t ah[3][4], al[3][4], bh[2][4], bl[2][4];
            #pragma unroll
            for (int mf = 0; mf < 3; mf++) {
                uint32_t off = ((wm*48 + mf*16 + a_row)*ASTR + s*8 + a_koff) * 4;
                ldm_x4(ah[mf], abase + off);
                ldm_x4(al[mf], abase + A_HALF*4 + off);
            }
            #pragma unroll
            for (int np = 0; np < 2; np++) {
                uint32_t off = (uint32_t)(s*16 + b_kr) * B_ROWB
                             + (uint32_t)(wn*32 + np*16 + b_noff) * 2;
                ldm_x4t(bh[np], bbase + off);
                ldm_x4t(bl[np], bbase + B_HALF*4 + off);
            }
            #pragma unroll
            for (int mf = 0; mf < 3; mf++)
                #pragma unroll
                for (int nf = 0; nf < 4; nf++) {
                    const uint32_t* pbh = &bh[nf>>1][(nf&1)*2];
                    const uint32_t* pbl = &bl[nf>>1][(nf&1)*2];
                    mma_bf16(acc[mf][nf], ah[mf], pbh);
                    mma_bf16(acc[mf][nf], ah[mf], pbl);
                    mma_bf16(acc[mf][nf], al[mf], pbh);
                }
        }
        CP_WAIT0();
        __syncthreads();
    }

    /* epilogue */
    #pragma unroll
    for (int mf = 0; mf < 3; mf++) {
        int mr = wm*48 + mf*16 + grp;
        float bz0 = __ldg(&bias[mr]);
        float bz1 = __ldg(&bias[mr + 8]);
        #pragma unroll
        for (int nf = 0; nf < 4; nf++) {
            int n = n0 + wn*32 + nf*8 + tig*2;
            float x0 = acc[mf][nf][0] + bz0, x1 = acc[mf][nf][1] + bz0;
            float x2 = acc[mf][nf][2] + bz1, x3 = acc[mf][nf][3] + bz1;
            if (!OUT_SPLIT) {
                float* Yb = Yf + (size_t)b * SZB;
                *(float2*)&Yb[(size_t)mr * HW + n]       = make_float2(x0, x1);
                *(float2*)&Yb[(size_t)(mr + 8) * HW + n] = make_float2(x2, x3);
            } else {
                __nv_bfloat16* Ybh = Yh + (size_t)b * SZB;
                __nv_bfloat16* Ybl = Yl + (size_t)b * SZB;
                uint32_t u0 = __float_as_uint(x0), u1 = __float_as_uint(x1);
                uint32_t u2 = __float_as_uint(x2), u3 = __float_as_uint(x3);
                uint32_t hv0 = __byte_perm(u0, u1, 0x7632);
                uint32_t hv1 = __byte_perm(u2, u3, 0x7632);
                __nv_bfloat162 l0 = __floats2bfloat162_rn(
                    x0 - __uint_as_float(u0 & 0xFFFF0000u),
                    x1 - __uint_as_float(u1 & 0xFFFF0000u));
                __nv_bfloat162 l1 = __floats2bfloat162_rn(
                    x2 - __uint_as_float(u2 & 0xFFFF0000u),
                    x3 - __uint_as_float(u3 & 0xFFFF0000u));
                *(uint32_t*)&Ybh[(size_t)mr * HW + n]       = hv0;
                *(uint32_t*)&Ybh[(size_t)(mr + 8) * HW + n] = hv1;
                *(uint32_t*)&Ybl[(size_t)mr * HW + n]       = *reinterpret_cast<uint32_t*>(&l0);
                *(uint32_t*)&Ybl[(size_t)(mr + 8) * HW + n] = *reinterpret_cast<uint32_t*>(&l1);
            }
        }
    }
}

/* ------------------------------------------------------------------ */
/* Fused raw logits + row sum-of-squares, float4-vectorized.           */
/* ------------------------------------------------------------------ */
__global__ void __launch_bounds__(256)
attn_kernel(const float* __restrict__ qp, const float* __restrict__ kp)
{
    const int bh   = blockIdx.x;
    const int ch   = blockIdx.y;
    const int warp = threadIdx.x >> 5;
    const int lane = threadIdx.x & 31;
    const int b  = bh / HEADS;
    const int hh = bh % HEADS;

    const float* Q = qp + (size_t)(b*CDIM + hh*CH) * HW;
    const float* K = kp + (size_t)(b*CDIM + hh*CH) * HW;
    const int c0 = warp * 4;

    float acc[4][32];
    #pragma unroll
    for (int i = 0; i < 4; i++)
        #pragma unroll
        for (int d = 0; d < 32; d++) acc[i][d] = 0.f;
    float qs[4] = {0.f,0.f,0.f,0.f};
    float ks[4] = {0.f,0.f,0.f,0.f};

    const int v0 = (ch * ATT_CHUNK) >> 2;
    for (int n = v0 + lane; n < v0 + (ATT_CHUNK >> 2); n += 32) {
        float4 qv[4];
        #pragma unroll
        for (int i = 0; i < 4; i++) {
            qv[i] = ((const float4*)(Q + (size_t)(c0 + i) * HW))[n];
            qs[i] += qv[i].x*qv[i].x + qv[i].y*qv[i].y
                   + qv[i].z*qv[i].z + qv[i].w*qv[i].w;
        }
        #pragma unroll
        for (int i = 0; i < 4; i++) {
            float4 kc = ((const float4*)(K + (size_t)(c0 + i) * HW))[n];
            ks[i] += kc.x*kc.x + kc.y*kc.y + kc.z*kc.z + kc.w*kc.w;
        }
        #pragma unroll
        for (int d = 0; d < 32; d++) {
            float4 kv = ((const float4*)(K + (size_t)d * HW))[n];
            #pragma unroll
            for (int i = 0; i < 4; i++)
                acc[i][d] += qv[i].x*kv.x + qv[i].y*kv.y
                           + qv[i].z*kv.z + qv[i].w*kv.w;
        }
    }

    #pragma unroll
    for (int i = 0; i < 4; i++) {
        float out = 0.f;
        #pragma unroll
        for (int d = 0; d < 32; d++) {
            float v = acc[i][d];
            v += __shfl_xor_sync(0xffffffffu, v, 16);
            v += __shfl_xor_sync(0xffffffffu, v, 8);
            v += __shfl_xor_sync(0xffffffffu, v, 4);
            v += __shfl_xor_sync(0xffffffffu, v, 2);
            v += __shfl_xor_sync(0xffffffffu, v, 1);
            if (lane == d) out = v;
        }
        atomicAdd(&g_attn[bh*CH*CH + (c0 + i)*CH + lane], out);
    }

    #pragma unroll
    for (int i = 0; i < 4; i++) {
        float vq = qs[i], vk = ks[i];
        vq += __shfl_xor_sync(0xffffffffu, vq, 16);
        vq += __shfl_xor_sync(0xffffffffu, vq, 8);
        vq += __shfl_xor_sync(0xffffffffu, vq, 4);
        vq += __shfl_xor_sync(0xffffffffu, vq, 2);
        vq += __shfl_xor_sync(0xffffffffu, vq, 1);
        vk += __shfl_xor_sync(0xffffffffu, vk, 16);
        vk += __shfl_xor_sync(0xffffffffu, vk, 8);
        vk += __shfl_xor_sync(0xffffffffu, vk, 4);
        vk += __shfl_xor_sync(0xffffffffu, vk, 2);
        vk += __shfl_xor_sync(0xffffffffu, vk, 1);
        if (lane == 0) {
            int row = b*CDIM + hh*CH + c0 + i;
            atomicAdd(&g_ss[row], vq);
            atomicAdd(&g_ss[NROWS + row], vk);
        }
    }
}

/* ------------------------------------------------------------------ */
/* Softmax + Weff fold fused: block (b,h) computes P then its own
 * 192x32 slice of Weff = Wo(:,h-block) . P, emitting bf16 hi/lo.      */
/* ------------------------------------------------------------------ */
__global__ void softmax_weff(const float* __restrict__ temp,
                             const float* __restrict__ wo)
{
    __shared__ float P[32*33];
    const int bh = blockIdx.x;
    const int b  = bh / HEADS;
    const int hh = bh % HEADS;
    const int tx = threadIdx.x;       /* d / dc */
    const int ty = threadIdx.y;       /* c / o-base */

    const int rowq = b*CDIM + hh*CH + ty;
    const int rowk = b*CDIM + hh*CH + tx;
    float rq = 1.f / fmaxf(sqrtf(g_ss[rowq]), 1e-12f);
    float rk = 1.f / fmaxf(sqrtf(g_ss[NROWS + rowk]), 1e-12f);

    float v = g_attn[bh*CH*CH + ty*CH + tx] * rq * rk * temp[hh];

    float m = v;
    m = fmaxf(m, __shfl_xor_sync(0xffffffffu, m, 16));
    m = fmaxf(m, __shfl_xor_sync(0xffffffffu, m, 8));
    m = fmaxf(m, __shfl_xor_sync(0xffffffffu, m, 4));
    m = fmaxf(m, __shfl_xor_sync(0xffffffffu, m, 2));
    m = fmaxf(m, __shfl_xor_sync(0xffffffffu, m, 1));
    float e = __expf(v - m);
    float s = e;
    s += __shfl_xor_sync(0xffffffffu, s, 16);
    s += __shfl_xor_sync(0xffffffffu, s, 8);
    s += __shfl_xor_sync(0xffffffffu, s, 4);
    s += __shfl_xor_sync(0xffffffffu, s, 2);
    s += __shfl_xor_sync(0xffffffffu, s, 1);
    P[ty*33 + tx] = e / s;
    __syncthreads();

    /* weff: this thread handles outputs (o = ty + 32*i, dc = tx) */
    #pragma unroll
    for (int i = 0; i < 6; i++) {
        int o = ty + 32*i;
        const float* wrow = wo + o*CDIM + hh*CH;
        float s2 = 0.f;
        #pragma unroll
        for (int c = 0; c < CH; c++)
            s2 += wrow[c] * P[c*33 + tx];
        size_t off = (size_t)b*WSZ + o*CDIM + hh*CH + tx;
        __nv_bfloat16 hw = __float2bfloat16(s2);
        g_weffh[off] = hw;
        g_weffl[off] = __float2bfloat16(s2 - __bfloat162float(hw));
    }
}

/* ------------------------------------------------------------------ */
extern "C" void kernel_launch(void* const* d_in, const int* in_sizes, int n_in,
                              void* d_out, int out_size)
{
    const float* q    = (const float*)d_in[0];
    const float* k    = (const float*)d_in[1];
    const float* v    = (const float*)d_in[2];
    const float* wq   = (const float*)d_in[3];
    const float* bq   = (const float*)d_in[4];
    const float* wk   = (const float*)d_in[5];
    const float* bk   = (const float*)d_in[6];
    const float* wv   = (const float*)d_in[7];
    const float* bv   = (const float*)d_in[8];
    const float* wo   = (const float*)d_in[9];
    const float* bo   = (const float*)d_in[10];
    const float* temp = (const float*)d_in[11];

    float *qp, *kp;
    __nv_bfloat16 *wh, *wl, *weh, *wel, *vph, *vpl;
    cudaGetSymbolAddress((void**)&qp,  g_qp);
    cudaGetSymbolAddress((void**)&kp,  g_kp);
    cudaGetSymbolAddress((void**)&wh,  g_wh);
    cudaGetSymbolAddress((void**)&wl,  g_wl);
    cudaGetSymbolAddress((void**)&weh, g_weffh);
    cudaGetSymbolAddress((void**)&wel, g_weffl);
    cudaGetSymbolAddress((void**)&vph, g_vph);
    cudaGetSymbolAddress((void**)&vpl, g_vpl);

    const int smem_bytes = S_WORDS * 4;
    cudaFuncSetAttribute(gemm_bf16<0,0>, cudaFuncAttributeMaxDynamicSharedMemorySize, smem_bytes);
    cudaFuncSetAttribute(gemm_bf16<0,1>, cudaFuncAttributeMaxDynamicSharedMemorySize, smem_bytes);
    cudaFuncSetAttribute(gemm_bf16<1,0>, cudaFuncAttributeMaxDynamicSharedMemorySize, smem_bytes);

    zero_kernel<<<(NBH*CH*CH + 255)/256, 256>>>();
    prep_w<<<(3*WSZ + 255)/256, 256>>>(wq, wk, wv);

    dim3 gg(HW/128, BATCH);
    gemm_bf16<0,0><<<gg, 512, smem_bytes>>>(q, (__nv_bfloat16*)0, (__nv_bfloat16*)0,
                                            wh + 0*WSZ, wl + 0*WSZ, bq,
                                            qp, (__nv_bfloat16*)0, (__nv_bfloat16*)0, 0);
    gemm_bf16<0,0><<<gg, 512, smem_bytes>>>(k, (__nv_bfloat16*)0, (__nv_bfloat16*)0,
                                            wh + 1*WSZ, wl + 1*WSZ, bk,
                                            kp, (__nv_bfloat16*)0, (__nv_bfloat16*)0, 0);
    gemm_bf16<0,1><<<gg, 512, smem_bytes>>>(v, (__nv_bfloat16*)0, (__nv_bfloat16*)0,
                                            wh + 2*WSZ, wl + 2*WSZ, bv,
                                            (float*)0, vph, vpl, 0);

    attn_kernel<<<dim3(NBH, ATT_CHUNKS), 256>>>(qp, kp);
    softmax_weff<<<NBH, dim3(32, 32)>>>(temp, wo);

    gemm_bf16<1,0><<<gg, 512, smem_bytes>>>((const float*)0, vph, vpl,
                                            weh, wel, bo,
                                            (float*)d_out, (__nv_bfloat16*)0,
                                            (__nv_bfloat16*)0, WSZ);
}

// round 17
// speedup vs baseline: 1.2396x; 1.0829x over previous
#include <cuda_runtime.h>
#include <cuda_bf16.h>
#include <cstdint>

#define HW    16384
#define BATCH 8
#define CDIM  192
#define HEADS 6
#define CH    32
#define NROWS (BATCH*CDIM)      /* 1536 */
#define NBH   (BATCH*HEADS)     /* 48   */
#define WSZ   (CDIM*CDIM)       /* 36864 */
#define SZB   (CDIM*HW)         /* 3145728 */
#define SZ    (BATCH*SZB)

/* ------------------------------------------------------------------ */
__device__ float g_qp[SZ];
__device__ float g_kp[SZ];
__device__ float g_attn[NBH*CH*CH];
__device__ float g_ss[2*NROWS];
__device__ __nv_bfloat16 g_wh[3*WSZ];
__device__ __nv_bfloat16 g_wl[3*WSZ];
__device__ __nv_bfloat16 g_weffh[BATCH*WSZ];
__device__ __nv_bfloat16 g_weffl[BATCH*WSZ];
__device__ __nv_bfloat16 g_vph[SZ];
__device__ __nv_bfloat16 g_vpl[SZ];

/* ------------------------------------------------------------------ */
__global__ void zero_kernel() {
    int i = blockIdx.x * 256 + threadIdx.x;
    if (i < NBH*CH*CH) g_attn[i] = 0.f;
    if (i < 2*NROWS)   g_ss[i]   = 0.f;
}

__global__ void prep_w(const float* __restrict__ wq,
                       const float* __restrict__ wk,
                       const float* __restrict__ wv)
{
    int i = blockIdx.x * 256 + threadIdx.x;
    if (i >= 3*WSZ) return;
    const float* src = (i < WSZ) ? wq : (i < 2*WSZ ? wk : wv);
    float x = src[i % WSZ];
    __nv_bfloat16 h = __float2bfloat16(x);
    g_wh[i] = h;
    g_wl[i] = __float2bfloat16(x - __bfloat162float(h));
}

/* ------------------------------------------------------------------ */
#define ASTR   36
#define A_HALF (192*ASTR)
#define A_BUFW (2*A_HALF)
#define B_ROWB 272
#define B_HALF (64*68)
#define B_BUFW (2*B_HALF)
#define SA_W(buf) ((buf)*A_BUFW)
#define SB_W(buf) (2*A_BUFW + (buf)*B_BUFW)
#define S_WORDS (2*A_BUFW + 2*B_BUFW)  /* 45056 words = 180224 B */

__device__ __forceinline__ uint32_t smem_u32(const void* p) {
    uint32_t a;
    asm("{ .reg .u64 t; cvta.to.shared.u64 t, %1; cvt.u32.u64 %0, t; }"
        : "=r"(a) : "l"(p));
    return a;
}
__device__ __forceinline__ void cp16(uint32_t saddr, const void* g) {
    asm volatile("cp.async.cg.shared.global [%0], [%1], 16;"
                 :: "r"(saddr), "l"(g));
}
#define CP_COMMIT() asm volatile("cp.async.commit_group;" ::: "memory")
#define CP_WAIT0()  asm volatile("cp.async.wait_group 0;" ::: "memory")

__device__ __forceinline__ void ldm_x4(uint32_t* r, uint32_t addr) {
    asm volatile("ldmatrix.sync.aligned.m8n8.x4.shared.b16 {%0,%1,%2,%3}, [%4];"
        : "=r"(r[0]), "=r"(r[1]), "=r"(r[2]), "=r"(r[3]) : "r"(addr));
}
__device__ __forceinline__ void ldm_x4t(uint32_t* r, uint32_t addr) {
    asm volatile("ldmatrix.sync.aligned.m8n8.x4.trans.shared.b16 {%0,%1,%2,%3}, [%4];"
        : "=r"(r[0]), "=r"(r[1]), "=r"(r[2]), "=r"(r[3]) : "r"(addr));
}
__device__ __forceinline__ void mma_bf16(float* c, const uint32_t* a, const uint32_t* b) {
    asm volatile(
        "mma.sync.aligned.m16n8k16.row.col.f32.bf16.bf16.f32 "
        "{%0,%1,%2,%3}, {%4,%5,%6,%7}, {%8,%9}, {%0,%1,%2,%3};"
        : "+f"(c[0]), "+f"(c[1]), "+f"(c[2]), "+f"(c[3])
        : "r"(a[0]), "r"(a[1]), "r"(a[2]), "r"(a[3]), "r"(b[0]), "r"(b[1]));
}

template<int IN_SPLIT, int OUT_SPLIT>
__global__ void __launch_bounds__(512, 1)
gemm_bf16(const float* __restrict__ Xf,
          const __nv_bfloat16* __restrict__ Xhi,
          const __nv_bfloat16* __restrict__ Xlo,
          const __nv_bfloat16* __restrict__ Whi,
          const __nv_bfloat16* __restrict__ Wlo,
          const float* __restrict__ bias,
          float* __restrict__ Yf,
          __nv_bfloat16* __restrict__ Yh,
          __nv_bfloat16* __restrict__ Yl,
          int wstride)
{
    extern __shared__ uint32_t sm[];
    char* smc = (char*)sm;
    const uint32_t sbase = smem_u32(sm);

    const int tid  = threadIdx.x;
    const int wid  = tid >> 5;
    const int lane = tid & 31;
    const int grp  = lane >> 2;
    const int tig  = lane & 3;
    const int wm   = wid & 3;
    const int wn   = wid >> 2;

    const int n0 = blockIdx.x * 128;
    const int b  = blockIdx.y;

    const float* Xbf = Xf ? Xf + (size_t)b * SZB : (const float*)0;
    const __nv_bfloat16* Xbh = Xhi ? Xhi + (size_t)b * SZB : (const __nv_bfloat16*)0;
    const __nv_bfloat16* Xbl = Xlo ? Xlo + (size_t)b * SZB : (const __nv_bfloat16*)0;
    const __nv_bfloat16* Wh  = Whi + (size_t)b * wstride;
    const __nv_bfloat16* Wl  = Wlo + (size_t)b * wstride;

    const int a_row  = lane & 15;
    const int a_koff = (lane >> 4) * 4;
    const int b_kr   = lane & 15;
    const int b_noff = (lane >> 4) * 8;

    float acc[3][4][4];
    #pragma unroll
    for (int i = 0; i < 3; i++)
        #pragma unroll
        for (int j = 0; j < 4; j++)
            #pragma unroll
            for (int r = 0; r < 4; r++) acc[i][j][r] = 0.f;

    auto stage = [&](int k0, int buf) {
        #pragma unroll
        for (int r = 0; r < 3; r++) {
            int j = tid + 512*r;
            int m = j >> 3, kg = j & 7;
            cp16(sbase + (SA_W(buf) + m*ASTR + kg*4)*4, Wh + m*CDIM + k0 + 8*kg);
            cp16(sbase + (SA_W(buf) + A_HALF + m*ASTR + kg*4)*4, Wl + m*CDIM + k0 + 8*kg);
        }
        if (IN_SPLIT) {
            #pragma unroll
            for (int r = 0; r < 2; r++) {
                int j = tid + 512*r;
                int k = j >> 4, jg = j & 15;
                cp16(sbase + SB_W(buf)*4 + k*B_ROWB + jg*16,
                     Xbh + (size_t)(k0 + k) * HW + n0 + 8*jg);
                cp16(sbase + (SB_W(buf) + B_HALF)*4 + k*B_ROWB + jg*16,
                     Xbl + (size_t)(k0 + k) * HW + n0 + 8*jg);
            }
        } else {
            #pragma unroll
            for (int r = 0; r < 2; r++) {
                int j = tid + 512*r;
                int k = j >> 4, seg = j & 15;
                const float* xp = Xbf + (size_t)(k0 + k) * HW + n0 + 8*seg;
                float4 xa = *(const float4*)xp;
                float4 xb = *(const float4*)(xp + 4);
                float xs[8] = {xa.x,xa.y,xa.z,xa.w,xb.x,xb.y,xb.z,xb.w};
                uint32_t hw4[4], lw4[4];
                #pragma unroll
                for (int p = 0; p < 4; p++) {
                    uint32_t b0 = __float_as_uint(xs[2*p]);
                    uint32_t b1 = __float_as_uint(xs[2*p+1]);
                    hw4[p] = __byte_perm(b0, b1, 0x7632);
                    float h0 = __uint_as_float(b0 & 0xFFFF0000u);
                    float h1 = __uint_as_float(b1 & 0xFFFF0000u);
                    __nv_bfloat162 lo2 = __floats2bfloat162_rn(xs[2*p] - h0, xs[2*p+1] - h1);
                    lw4[p] = *reinterpret_cast<uint32_t*>(&lo2);
                }
                *(uint4*)(smc + SB_W(buf)*4 + k*B_ROWB + seg*16) =
                    make_uint4(hw4[0],hw4[1],hw4[2],hw4[3]);
                *(uint4*)(smc + (SB_W(buf) + B_HALF)*4 + k*B_ROWB + seg*16) =
                    make_uint4(lw4[0],lw4[1],lw4[2],lw4[3]);
            }
        }
    };

    stage(0, 0);
    CP_COMMIT();
    CP_WAIT0();
    __syncthreads();

    for (int c = 0; c < 3; c++) {
        const int cur = c & 1;
        if (c < 2) { stage((c + 1) * 64, cur ^ 1); CP_COMMIT(); }

        const uint32_t abase = sbase + SA_W(cur)*4;
        const uint32_t bbase = sbase + SB_W(cur)*4;
        #pragma unroll
        for (int s = 0; s < 4; s++) {
            uint32_t ah[3][4], al[3][4], bh[2][4], bl[2][4];
            #pragma unroll
            for (int mf = 0; mf < 3; mf++) {
                uint32_t off = ((wm*48 + mf*16 + a_row)*ASTR + s*8 + a_koff) * 4;
                ldm_x4(ah[mf], abase + off);
                ldm_x4(al[mf], abase + A_HALF*4 + off);
            }
            #pragma unroll
            for (int np = 0; np < 2; np++) {
                uint32_t off = (uint32_t)(s*16 + b_kr) * B_ROWB
                             + (uint32_t)(wn*32 + np*16 + b_noff) * 2;
                ldm_x4t(bh[np], bbase + off);
                ldm_x4t(bl[np], bbase + B_HALF*4 + off);
            }
            #pragma unroll
            for (int mf = 0; mf < 3; mf++)
                #pragma unroll
                for (int nf = 0; nf < 4; nf++) {
                    const uint32_t* pbh = &bh[nf>>1][(nf&1)*2];
                    const uint32_t* pbl = &bl[nf>>1][(nf&1)*2];
                    mma_bf16(acc[mf][nf], ah[mf], pbh);
                    mma_bf16(acc[mf][nf], ah[mf], pbl);
                    mma_bf16(acc[mf][nf], al[mf], pbh);
                }
        }
        CP_WAIT0();
        __syncthreads();
    }

    #pragma unroll
    for (int mf = 0; mf < 3; mf++) {
        int mr = wm*48 + mf*16 + grp;
        float bz0 = __ldg(&bias[mr]);
        float bz1 = __ldg(&bias[mr + 8]);
        #pragma unroll
        for (int nf = 0; nf < 4; nf++) {
            int n = n0 + wn*32 + nf*8 + tig*2;
            float x0 = acc[mf][nf][0] + bz0, x1 = acc[mf][nf][1] + bz0;
            float x2 = acc[mf][nf][2] + bz1, x3 = acc[mf][nf][3] + bz1;
            if (!OUT_SPLIT) {
                float* Yb = Yf + (size_t)b * SZB;
                *(float2*)&Yb[(size_t)mr * HW + n]       = make_float2(x0, x1);
                *(float2*)&Yb[(size_t)(mr + 8) * HW + n] = make_float2(x2, x3);
            } else {
                __nv_bfloat16* Ybh = Yh + (size_t)b * SZB;
                __nv_bfloat16* Ybl = Yl + (size_t)b * SZB;
                uint32_t u0 = __float_as_uint(x0), u1 = __float_as_uint(x1);
                uint32_t u2 = __float_as_uint(x2), u3 = __float_as_uint(x3);
                uint32_t hv0 = __byte_perm(u0, u1, 0x7632);
                uint32_t hv1 = __byte_perm(u2, u3, 0x7632);
                __nv_bfloat162 l0 = __floats2bfloat162_rn(
                    x0 - __uint_as_float(u0 & 0xFFFF0000u),
                    x1 - __uint_as_float(u1 & 0xFFFF0000u));
                __nv_bfloat162 l1 = __floats2bfloat162_rn(
                    x2 - __uint_as_float(u2 & 0xFFFF0000u),
                    x3 - __uint_as_float(u3 & 0xFFFF0000u));
                *(uint32_t*)&Ybh[(size_t)mr * HW + n]       = hv0;
                *(uint32_t*)&Ybh[(size_t)(mr + 8) * HW + n] = hv1;
                *(uint32_t*)&Ybl[(size_t)mr * HW + n]       = *reinterpret_cast<uint32_t*>(&l0);
                *(uint32_t*)&Ybl[(size_t)(mr + 8) * HW + n] = *reinterpret_cast<uint32_t*>(&l1);
            }
        }
    }
}

/* ------------------------------------------------------------------ */
/* Tensor-core logits: block = (bh, 1/16 of HW = 1024 elems).
 * 256 thr / 8 warps; warp w owns k16-step w of each 128-elem subchunk.
 * fp32 -> bf16 hi/lo truncation split into [row][kpair] tiles (pitch
 * 272B), double-buffered, one barrier per subchunk. 3-split MMA into
 * per-warp 32x32 partials; smem-atomic reduce; 4 global atomics/thr.
 * Sumsq computed exactly from fp32 during convert.                    */
/* ------------------------------------------------------------------ */
#define AT_P    68                       /* tile row pitch, words */
#define AT_HALF (32*AT_P)                /* 2176 words */
#define AT_QH(buf) ((buf)*4*AT_HALF)
#define AT_QL(buf) (AT_QH(buf) + AT_HALF)
#define AT_KH(buf) (AT_QH(buf) + 2*AT_HALF)
#define AT_KL(buf) (AT_QH(buf) + 3*AT_HALF)
#define AT_RED  (8*AT_HALF)              /* 17408 */
#define AT_WORDS (AT_RED + 32*33)        /* 18464 words = 73856 B */

__global__ void __launch_bounds__(256)
attn_tc(const float* __restrict__ qp, const float* __restrict__ kp)
{
    extern __shared__ uint32_t sm[];
    float* smf = (float*)sm;
    const uint32_t sbase = smem_u32(sm);

    const int bh   = blockIdx.x;
    const int kb   = blockIdx.y;          /* 0..15 */
    const int tid  = threadIdx.x;
    const int wid  = tid >> 5;            /* 0..7: kstep owner */
    const int lane = tid & 31;
    const int grp  = lane >> 2;
    const int tig  = lane & 3;
    const int b  = bh / HEADS;
    const int hh = bh % HEADS;

    const float* Q = qp + (size_t)(b*CDIM + hh*CH) * HW + kb*1024;
    const float* K = kp + (size_t)(b*CDIM + hh*CH) * HW + kb*1024;

    const int row = tid >> 3;             /* 0..31 */
    const int seg = tid & 7;              /* 16 elems each */

    /* zero reduce buffer */
    for (int i = tid; i < 32*33; i += 256) smf[AT_RED + i] = 0.f;

    float qss = 0.f, kss = 0.f;

    auto stage = [&](int sub, int buf) {
        const float* qs = Q + (size_t)row * HW + sub*128 + seg*16;
        const float* ks = K + (size_t)row * HW + sub*128 + seg*16;
        #pragma unroll
        for (int t = 0; t < 2; t++) {     /* t=0: q, t=1: k */
            const float* src = t ? ks : qs;
            uint32_t hbase = t ? AT_KH(buf) : AT_QH(buf);
            uint32_t lbase = t ? AT_KL(buf) : AT_QL(buf);
            #pragma unroll
            for (int half = 0; half < 2; half++) {  /* 8 elems each */
                float4 xa = *(const float4*)(src + half*8);
                float4 xb = *(const float4*)(src + half*8 + 4);
                float xs[8] = {xa.x,xa.y,xa.z,xa.w,xb.x,xb.y,xb.z,xb.w};
                uint32_t hw4[4], lw4[4];
                float ss = 0.f;
                #pragma unroll
                for (int p = 0; p < 4; p++) {
                    ss += xs[2*p]*xs[2*p] + xs[2*p+1]*xs[2*p+1];
                    uint32_t b0 = __float_as_uint(xs[2*p]);
                    uint32_t b1 = __float_as_uint(xs[2*p+1]);
                    hw4[p] = __byte_perm(b0, b1, 0x7632);
                    float h0 = __uint_as_float(b0 & 0xFFFF0000u);
                    float h1 = __uint_as_float(b1 & 0xFFFF0000u);
                    __nv_bfloat162 lo2 = __floats2bfloat162_rn(xs[2*p] - h0, xs[2*p+1] - h1);
                    lw4[p] = *reinterpret_cast<uint32_t*>(&lo2);
                }
                if (t) kss += ss; else qss += ss;
                uint32_t woff = (uint32_t)row*AT_P + seg*8 + half*4;
                *(uint4*)&sm[hbase + woff] = make_uint4(hw4[0],hw4[1],hw4[2],hw4[3]);
                *(uint4*)&sm[lbase + woff] = make_uint4(lw4[0],lw4[1],lw4[2],lw4[3]);
            }
        }
    };

    const int a_row  = lane & 15;
    const int a_koff = (lane >> 4) * 4;
    const int b_row  = (lane & 7) + ((lane >> 4) << 3);
    const int b_koff = ((lane >> 3) & 1) * 4;

    float acc[2][4][4];
    #pragma unroll
    for (int i = 0; i < 2; i++)
        #pragma unroll
        for (int j = 0; j < 4; j++)
            #pragma unroll
            for (int r = 0; r < 4; r++) acc[i][j][r] = 0.f;

    stage(0, 0);
    __syncthreads();

    for (int s = 0; s < 8; s++) {
        const int cur = s & 1;
        if (s < 7) stage(s + 1, cur ^ 1);

        const uint32_t kw = (uint32_t)wid * 8;   /* kpair offset of this warp's kstep */
        uint32_t ah[2][4], al[2][4], bhf[2][4], blf[2][4];
        #pragma unroll
        for (int mf = 0; mf < 2; mf++) {
            uint32_t off = ((mf*16 + a_row)*AT_P + kw + a_koff) * 4;
            ldm_x4(ah[mf], sbase + AT_QH(cur)*4 + off);
            ldm_x4(al[mf], sbase + AT_QL(cur)*4 + off);
        }
        #pragma unroll
        for (int np = 0; np < 2; np++) {
            uint32_t off = ((np*16 + b_row)*AT_P + kw + b_koff) * 4;
            ldm_x4(bhf[np], sbase + AT_KH(cur)*4 + off);
            ldm_x4(blf[np], sbase + AT_KL(cur)*4 + off);
        }
        #pragma unroll
        for (int mf = 0; mf < 2; mf++)
            #pragma unroll
            for (int nf = 0; nf < 4; nf++) {
                const uint32_t* pbh = &bhf[nf>>1][(nf&1)*2];
                const uint32_t* pbl = &blf[nf>>1][(nf&1)*2];
                mma_bf16(acc[mf][nf], ah[mf], pbh);
                mma_bf16(acc[mf][nf], ah[mf], pbl);
                mma_bf16(acc[mf][nf], al[mf], pbh);
            }
        __syncthreads();
    }

    /* reduce logits across warps via smem atomics */
    #pragma unroll
    for (int mf = 0; mf < 2; mf++) {
        int r0 = mf*16 + grp;
        #pragma unroll
        for (int nf = 0; nf < 4; nf++) {
            int cc = nf*8 + tig*2;
            atomicAdd(&smf[AT_RED + r0*33 + cc],       acc[mf][nf][0]);
            atomicAdd(&smf[AT_RED + r0*33 + cc + 1],   acc[mf][nf][1]);
            atomicAdd(&smf[AT_RED + (r0+8)*33 + cc],   acc[mf][nf][2]);
            atomicAdd(&smf[AT_RED + (r0+8)*33 + cc+1], acc[mf][nf][3]);
        }
    }
    /* sumsq: reduce across the 8 threads sharing a row (same warp) */
    qss += __shfl_xor_sync(0xffffffffu, qss, 1);
    qss += __shfl_xor_sync(0xffffffffu, qss, 2);
    qss += __shfl_xor_sync(0xffffffffu, qss, 4);
    kss += __shfl_xor_sync(0xffffffffu, kss, 1);
    kss += __shfl_xor_sync(0xffffffffu, kss, 2);
    kss += __shfl_xor_sync(0xffffffffu, kss, 4);
    if ((lane & 7) == 0) {
        int rowglob = b*CDIM + hh*CH + row;
        atomicAdd(&g_ss[rowglob], qss);
        atomicAdd(&g_ss[NROWS + rowglob], kss);
    }
    __syncthreads();

    for (int i = tid*4; i < tid*4 + 4; i++) {
        int r = i >> 5, cc = i & 31;
        atomicAdd(&g_attn[bh*CH*CH + i], smf[AT_RED + r*33 + cc]);
    }
}

/* ------------------------------------------------------------------ */
/* Softmax + Weff fold fused (unchanged from R16).                     */
/* ------------------------------------------------------------------ */
__global__ void softmax_weff(const float* __restrict__ temp,
                             const float* __restrict__ wo)
{
    __shared__ float P[32*33];
    const int bh = blockIdx.x;
    const int b  = bh / HEADS;
    const int hh = bh % HEADS;
    const int tx = threadIdx.x;
    const int ty = threadIdx.y;

    const int rowq = b*CDIM + hh*CH + ty;
    const int rowk = b*CDIM + hh*CH + tx;
    float rq = 1.f / fmaxf(sqrtf(g_ss[rowq]), 1e-12f);
    float rk = 1.f / fmaxf(sqrtf(g_ss[NROWS + rowk]), 1e-12f);

    float v = g_attn[bh*CH*CH + ty*CH + tx] * rq * rk * temp[hh];

    float m = v;
    m = fmaxf(m, __shfl_xor_sync(0xffffffffu, m, 16));
    m = fmaxf(m, __shfl_xor_sync(0xffffffffu, m, 8));
    m = fmaxf(m, __shfl_xor_sync(0xffffffffu, m, 4));
    m = fmaxf(m, __shfl_xor_sync(0xffffffffu, m, 2));
    m = fmaxf(m, __shfl_xor_sync(0xffffffffu, m, 1));
    float e = __expf(v - m);
    float s = e;
    s += __shfl_xor_sync(0xffffffffu, s, 16);
    s += __shfl_xor_sync(0xffffffffu, s, 8);
    s += __shfl_xor_sync(0xffffffffu, s, 4);
    s += __shfl_xor_sync(0xffffffffu, s, 2);
    s += __shfl_xor_sync(0xffffffffu, s, 1);
    P[ty*33 + tx] = e / s;
    __syncthreads();

    #pragma unroll
    for (int i = 0; i < 6; i++) {
        int o = ty + 32*i;
        const float* wrow = wo + o*CDIM + hh*CH;
        float s2 = 0.f;
        #pragma unroll
        for (int c = 0; c < CH; c++)
            s2 += wrow[c] * P[c*33 + tx];
        size_t off = (size_t)b*WSZ + o*CDIM + hh*CH + tx;
        __nv_bfloat16 hw = __float2bfloat16(s2);
        g_weffh[off] = hw;
        g_weffl[off] = __float2bfloat16(s2 - __bfloat162float(hw));
    }
}

/* ------------------------------------------------------------------ */
extern "C" void kernel_launch(void* const* d_in, const int* in_sizes, int n_in,
                              void* d_out, int out_size)
{
    const float* q    = (const float*)d_in[0];
    const float* k    = (const float*)d_in[1];
    const float* v    = (const float*)d_in[2];
    const float* wq   = (const float*)d_in[3];
    const float* bq   = (const float*)d_in[4];
    const float* wk   = (const float*)d_in[5];
    const float* bk   = (const float*)d_in[6];
    const float* wv   = (const float*)d_in[7];
    const float* bv   = (const float*)d_in[8];
    const float* wo   = (const float*)d_in[9];
    const float* bo   = (const float*)d_in[10];
    const float* temp = (const float*)d_in[11];

    float *qp, *kp;
    __nv_bfloat16 *wh, *wl, *weh, *wel, *vph, *vpl;
    cudaGetSymbolAddress((void**)&qp,  g_qp);
    cudaGetSymbolAddress((void**)&kp,  g_kp);
    cudaGetSymbolAddress((void**)&wh,  g_wh);
    cudaGetSymbolAddress((void**)&wl,  g_wl);
    cudaGetSymbolAddress((void**)&weh, g_weffh);
    cudaGetSymbolAddress((void**)&wel, g_weffl);
    cudaGetSymbolAddress((void**)&vph, g_vph);
    cudaGetSymbolAddress((void**)&vpl, g_vpl);

    const int smem_bytes = S_WORDS * 4;
    const int at_bytes   = AT_WORDS * 4;
    cudaFuncSetAttribute(gemm_bf16<0,0>, cudaFuncAttributeMaxDynamicSharedMemorySize, smem_bytes);
    cudaFuncSetAttribute(gemm_bf16<0,1>, cudaFuncAttributeMaxDynamicSharedMemorySize, smem_bytes);
    cudaFuncSetAttribute(gemm_bf16<1,0>, cudaFuncAttributeMaxDynamicSharedMemorySize, smem_bytes);
    cudaFuncSetAttribute(attn_tc, cudaFuncAttributeMaxDynamicSharedMemorySize, at_bytes);

    zero_kernel<<<(NBH*CH*CH + 255)/256, 256>>>();
    prep_w<<<(3*WSZ + 255)/256, 256>>>(wq, wk, wv);

    dim3 gg(HW/128, BATCH);
    gemm_bf16<0,0><<<gg, 512, smem_bytes>>>(q, (__nv_bfloat16*)0, (__nv_bfloat16*)0,
                                            wh + 0*WSZ, wl + 0*WSZ, bq,
                                            qp, (__nv_bfloat16*)0, (__nv_bfloat16*)0, 0);
    gemm_bf16<0,0><<<gg, 512, smem_bytes>>>(k, (__nv_bfloat16*)0, (__nv_bfloat16*)0,
                                            wh + 1*WSZ, wl + 1*WSZ, bk,
                                            kp, (__nv_bfloat16*)0, (__nv_bfloat16*)0, 0);
    gemm_bf16<0,1><<<gg, 512, smem_bytes>>>(v, (__nv_bfloat16*)0, (__nv_bfloat16*)0,
                                            wh + 2*WSZ, wl + 2*WSZ, bv,
                                            (float*)0, vph, vpl, 0);

    attn_tc<<<dim3(NBH, 16), 256, at_bytes>>>(qp, kp);
    softmax_weff<<<NBH, dim3(32, 32)>>>(temp, wo);

    gemm_bf16<1,0><<<gg, 512, smem_bytes>>>((const float*)0, vph, vpl,
                                            weh, wel, bo,
                                            (float*)d_out, (__nv_bfloat16*)0,
                                            (__nv_bfloat16*)0, WSZ);
}